// round 1
// baseline (speedup 1.0000x reference)
#include <cuda_runtime.h>
#include <cuda_bf16.h>
#include <cstdint>
#include <cstddef>

// Problem constants
#define T_TOK 4096
#define D_DIM 1024
#define F_DIM 2816
#define F2_DIM 5632
#define N_EXP 8
#define K_SLOT 2
#define TK (T_TOK * K_SLOT)   // 8192 routed entries

// Tiling
#define BM 128
#define BN 64
#define BK 32
#define PAD 4
#define LDA (BK + PAD)        // 36 floats per smem row

// ---------------- device scratch (no allocations allowed) ----------------
__device__ int   g_offsets[N_EXP + 1];
__device__ int   g_tok[TK];
__device__ float g_wt[TK];
__device__ float g_h[(size_t)TK * F_DIM];   // 92.3 MB intermediate SwiGLU output

// ---------------- helpers ----------------
__device__ __forceinline__ unsigned f2tf(float x) {
    unsigned r;
    asm("cvt.rna.tf32.f32 %0, %1;" : "=r"(r) : "f"(x));
    return r;
}

__device__ __forceinline__ void mma_tf32(float c[4], const unsigned a[4], const unsigned b[2]) {
    asm volatile(
        "mma.sync.aligned.m16n8k8.row.col.f32.tf32.tf32.f32 "
        "{%0,%1,%2,%3},{%4,%5,%6,%7},{%8,%9},{%0,%1,%2,%3};"
        : "+f"(c[0]), "+f"(c[1]), "+f"(c[2]), "+f"(c[3])
        : "r"(a[0]), "r"(a[1]), "r"(a[2]), "r"(a[3]), "r"(b[0]), "r"(b[1]));
}

__device__ __forceinline__ void cpasync16(void* smem_ptr, const void* gptr) {
    unsigned s = (unsigned)__cvta_generic_to_shared(smem_ptr);
    asm volatile("cp.async.cg.shared.global [%0], [%1], 16;" ::"r"(s), "l"(gptr));
}
__device__ __forceinline__ void cp_commit() { asm volatile("cp.async.commit_group;"); }
__device__ __forceinline__ void cp_wait0() { asm volatile("cp.async.wait_group 0;"); }

// ---------------- zero output ----------------
__global__ void zero_kernel(float4* p, int n4) {
    int i = blockIdx.x * blockDim.x + threadIdx.x;
    if (i < n4) p[i] = make_float4(0.f, 0.f, 0.f, 0.f);
}

// ---------------- routing: bucket entries by expert ----------------
__global__ void routing_kernel(const void* sel_raw, const float* __restrict__ rw) {
    __shared__ int sc[N_EXP];
    __shared__ int scur[N_EXP];
    __shared__ int smode;  // 1 = int64, 0 = int32
    int tid = threadIdx.x;
    if (tid < N_EXP) sc[tid] = 0;
    if (tid == 0) {
        // int64 little-endian values 0..7 have zero high words; detect.
        const int* s32 = (const int*)sel_raw;
        int any = 0;
        #pragma unroll
        for (int i = 0; i < 8; i++) any |= s32[2 * i + 1];
        smode = any ? 0 : 1;
    }
    __syncthreads();
    int mode = smode;
    const long long* s64 = (const long long*)sel_raw;
    const int* s32 = (const int*)sel_raw;
    for (int i = tid; i < TK; i += blockDim.x) {
        int e = mode ? (int)s64[i] : s32[i];
        atomicAdd(&sc[e], 1);
    }
    __syncthreads();
    if (tid == 0) {
        int off = 0;
        for (int e = 0; e < N_EXP; e++) {
            g_offsets[e] = off;
            scur[e] = off;
            off += sc[e];
        }
        g_offsets[N_EXP] = off;  // == TK
    }
    __syncthreads();
    for (int i = tid; i < TK; i += blockDim.x) {
        int e = mode ? (int)s64[i] : s32[i];
        int p = atomicAdd(&scur[e], 1);
        g_tok[p] = i >> 1;     // token index (K_SLOT == 2)
        g_wt[p] = rw[i];
    }
}

// ---------------- GEMM1: gate_up + SwiGLU -> g_h ----------------
// C_gate[i,j] = sum_d X[tok_i,d] * Wgu[e, col0+j, d]
// C_up  [i,j] = sum_d X[tok_i,d] * Wgu[e, F + col0+j, d]
// h = silu(gate) * up
__global__ void __launch_bounds__(256, 2)
gemm1_kernel(const float* __restrict__ X, const float* __restrict__ Wgu) {
    const int e = blockIdx.z;
    const int base = g_offsets[e];
    const int n_e = g_offsets[e + 1] - base;
    const int row0 = blockIdx.x * BM;
    if (row0 >= n_e) return;
    const int col0 = blockIdx.y * BN;

    extern __shared__ float sm[];
    float* As = sm;                          // 2 * BM*LDA = 2*4608
    float* Bg = sm + 2 * BM * LDA;           // 2 * BN*LDA = 2*2304
    float* Bu = sm + 2 * BM * LDA + 2 * BN * LDA;
    __shared__ int toks[BM];

    const int tid = threadIdx.x;
    if (tid < BM) {
        int ge = base + row0 + tid;
        if (ge > TK - 1) ge = TK - 1;
        toks[tid] = g_tok[ge];
    }
    __syncthreads();

    const int lane = tid & 31, warp = tid >> 5;
    const int wm = warp >> 1, wn = warp & 1;

    // per-thread load mapping (fixed row/col, k advances)
    const int lr = tid >> 3;
    const int lc = (tid & 7) * 4;
    const float* a_src[4];
    #pragma unroll
    for (int i = 0; i < 4; i++)
        a_src[i] = X + (size_t)toks[lr + 32 * i] * D_DIM + lc;
    const float* bg_src[2];
    const float* bu_src[2];
    #pragma unroll
    for (int i = 0; i < 2; i++) {
        bg_src[i] = Wgu + ((size_t)e * F2_DIM + (col0 + lr + 32 * i)) * D_DIM + lc;
        bu_src[i] = Wgu + ((size_t)e * F2_DIM + F_DIM + (col0 + lr + 32 * i)) * D_DIM + lc;
    }
    const int sa_off = lr * LDA + lc;
    const int sb_off = lr * LDA + lc;

    float cg[2][4][4], cu[2][4][4];
    #pragma unroll
    for (int a = 0; a < 2; a++)
        #pragma unroll
        for (int b = 0; b < 4; b++)
            #pragma unroll
            for (int c = 0; c < 4; c++) { cg[a][b][c] = 0.f; cu[a][b][c] = 0.f; }

    auto issue = [&](int kt, int buf) {
        const int k0 = kt * BK;
        float* as = As + buf * BM * LDA;
        float* bgs = Bg + buf * BN * LDA;
        float* bus = Bu + buf * BN * LDA;
        #pragma unroll
        for (int i = 0; i < 4; i++)
            cpasync16(as + sa_off + i * 32 * LDA, a_src[i] + k0);
        #pragma unroll
        for (int i = 0; i < 2; i++) {
            cpasync16(bgs + sb_off + i * 32 * LDA, bg_src[i] + k0);
            cpasync16(bus + sb_off + i * 32 * LDA, bu_src[i] + k0);
        }
        cp_commit();
    };

    issue(0, 0);
    const int KT = D_DIM / BK;  // 32
    for (int kt = 0; kt < KT; kt++) {
        cp_wait0();
        __syncthreads();
        if (kt + 1 < KT) issue(kt + 1, (kt + 1) & 1);
        const float* as = As + (kt & 1) * BM * LDA;
        const float* bgs = Bg + (kt & 1) * BN * LDA;
        const float* bus = Bu + (kt & 1) * BN * LDA;

        #pragma unroll
        for (int kk = 0; kk < 4; kk++) {
            const int k = kk * 8;
            unsigned a[2][4];
            #pragma unroll
            for (int mt = 0; mt < 2; mt++) {
                const float* ap = as + (wm * 32 + mt * 16 + (lane >> 2)) * LDA + k + (lane & 3);
                a[mt][0] = f2tf(ap[0]);
                a[mt][1] = f2tf(ap[8 * LDA]);
                a[mt][2] = f2tf(ap[4]);
                a[mt][3] = f2tf(ap[8 * LDA + 4]);
            }
            #pragma unroll
            for (int nt = 0; nt < 4; nt++) {
                const int cb = wn * 32 + nt * 8;
                const float* gp = bgs + (cb + (lane >> 2)) * LDA + k + (lane & 3);
                const float* up = bus + (cb + (lane >> 2)) * LDA + k + (lane & 3);
                unsigned bgf[2] = { f2tf(gp[0]), f2tf(gp[4]) };
                unsigned buf2[2] = { f2tf(up[0]), f2tf(up[4]) };
                #pragma unroll
                for (int mt = 0; mt < 2; mt++) {
                    mma_tf32(cg[mt][nt], a[mt], bgf);
                    mma_tf32(cu[mt][nt], a[mt], buf2);
                }
            }
        }
    }

    // epilogue: SwiGLU, store fp32 h
    #pragma unroll
    for (int mt = 0; mt < 2; mt++)
        #pragma unroll
        for (int nt = 0; nt < 4; nt++)
            #pragma unroll
            for (int h2 = 0; h2 < 2; h2++) {
                int lrow = wm * 32 + mt * 16 + (lane >> 2) + h2 * 8;
                if (row0 + lrow < n_e) {
                    int col = col0 + wn * 32 + nt * 8 + (lane & 3) * 2;
                    float g0 = cg[mt][nt][h2 * 2 + 0], g1 = cg[mt][nt][h2 * 2 + 1];
                    float u0 = cu[mt][nt][h2 * 2 + 0], u1 = cu[mt][nt][h2 * 2 + 1];
                    float h0 = g0 / (1.f + __expf(-g0)) * u0;
                    float h1 = g1 / (1.f + __expf(-g1)) * u1;
                    *(float2*)(g_h + (size_t)(base + row0 + lrow) * F_DIM + col) =
                        make_float2(h0, h1);
                }
            }
}

// ---------------- GEMM2: h @ Wd^T, scale by weight, scatter-add ----------------
__global__ void __launch_bounds__(256, 2)
gemm2_kernel(const float* __restrict__ Wd, float* __restrict__ out) {
    const int e = blockIdx.z;
    const int base = g_offsets[e];
    const int n_e = g_offsets[e + 1] - base;
    const int row0 = blockIdx.x * BM;
    if (row0 >= n_e) return;
    const int col0 = blockIdx.y * BN;  // over D

    extern __shared__ float sm[];
    float* As = sm;                 // 2 * BM*LDA
    float* Bs = sm + 2 * BM * LDA;  // 2 * BN*LDA
    __shared__ int toks[BM];
    __shared__ float wts[BM];

    const int tid = threadIdx.x;
    if (tid < BM) {
        int ge = base + row0 + tid;
        if (ge > TK - 1) ge = TK - 1;
        toks[tid] = g_tok[ge];
        wts[tid] = g_wt[ge];
    }
    __syncthreads();

    const int lane = tid & 31, warp = tid >> 5;
    const int wm = warp >> 1, wn = warp & 1;

    const int lr = tid >> 3;
    const int lc = (tid & 7) * 4;
    const float* a_src[4];
    #pragma unroll
    for (int i = 0; i < 4; i++) {
        int ge = base + row0 + lr + 32 * i;
        if (ge > TK - 1) ge = TK - 1;
        a_src[i] = g_h + (size_t)ge * F_DIM + lc;
    }
    const float* b_src[2];
    #pragma unroll
    for (int i = 0; i < 2; i++)
        b_src[i] = Wd + ((size_t)e * D_DIM + (col0 + lr + 32 * i)) * F_DIM + lc;
    const int sa_off = lr * LDA + lc;

    float cc_[2][4][4];
    #pragma unroll
    for (int a = 0; a < 2; a++)
        #pragma unroll
        for (int b = 0; b < 4; b++)
            #pragma unroll
            for (int c = 0; c < 4; c++) cc_[a][b][c] = 0.f;

    auto issue = [&](int kt, int buf) {
        const int k0 = kt * BK;
        float* as = As + buf * BM * LDA;
        float* bs = Bs + buf * BN * LDA;
        #pragma unroll
        for (int i = 0; i < 4; i++)
            cpasync16(as + sa_off + i * 32 * LDA, a_src[i] + k0);
        #pragma unroll
        for (int i = 0; i < 2; i++)
            cpasync16(bs + sa_off + i * 32 * LDA, b_src[i] + k0);
        cp_commit();
    };

    issue(0, 0);
    const int KT = F_DIM / BK;  // 88
    for (int kt = 0; kt < KT; kt++) {
        cp_wait0();
        __syncthreads();
        if (kt + 1 < KT) issue(kt + 1, (kt + 1) & 1);
        const float* as = As + (kt & 1) * BM * LDA;
        const float* bs = Bs + (kt & 1) * BN * LDA;

        #pragma unroll
        for (int kk = 0; kk < 4; kk++) {
            const int k = kk * 8;
            unsigned a[2][4];
            #pragma unroll
            for (int mt = 0; mt < 2; mt++) {
                const float* ap = as + (wm * 32 + mt * 16 + (lane >> 2)) * LDA + k + (lane & 3);
                a[mt][0] = f2tf(ap[0]);
                a[mt][1] = f2tf(ap[8 * LDA]);
                a[mt][2] = f2tf(ap[4]);
                a[mt][3] = f2tf(ap[8 * LDA + 4]);
            }
            #pragma unroll
            for (int nt = 0; nt < 4; nt++) {
                const int cb = wn * 32 + nt * 8;
                const float* bp = bs + (cb + (lane >> 2)) * LDA + k + (lane & 3);
                unsigned bf[2] = { f2tf(bp[0]), f2tf(bp[4]) };
                #pragma unroll
                for (int mt = 0; mt < 2; mt++)
                    mma_tf32(cc_[mt][nt], a[mt], bf);
            }
        }
    }

    // epilogue: scale by routing weight, scatter-add to output
    #pragma unroll
    for (int mt = 0; mt < 2; mt++)
        #pragma unroll
        for (int nt = 0; nt < 4; nt++)
            #pragma unroll
            for (int h2 = 0; h2 < 2; h2++) {
                int lrow = wm * 32 + mt * 16 + (lane >> 2) + h2 * 8;
                if (row0 + lrow < n_e) {
                    int col = col0 + wn * 32 + nt * 8 + (lane & 3) * 2;
                    int token = toks[lrow];
                    float w = wts[lrow];
                    atomicAdd(&out[(size_t)token * D_DIM + col],
                              cc_[mt][nt][h2 * 2 + 0] * w);
                    atomicAdd(&out[(size_t)token * D_DIM + col + 1],
                              cc_[mt][nt][h2 * 2 + 1] * w);
                }
            }
}

// ---------------- launch ----------------
extern "C" void kernel_launch(void* const* d_in, const int* in_sizes, int n_in,
                              void* d_out, int out_size) {
    const float* X   = (const float*)d_in[0];  // hidden_2d [T, D]
    const float* rw  = (const float*)d_in[1];  // routing_weights [T, K]
    const float* Wgu = (const float*)d_in[2];  // gate_up_proj [E, 2F, D]
    const float* Wd  = (const float*)d_in[3];  // down_proj [E, D, F]
    const void*  sel = d_in[4];                // selected_experts [T, K] (int64 or int32)
    float* out = (float*)d_out;

    const int smem1 = 2 * (BM * LDA + 2 * BN * LDA) * 4;  // 73728
    const int smem2 = 2 * (BM * LDA + BN * LDA) * 4;      // 55296
    cudaFuncSetAttribute(gemm1_kernel, cudaFuncAttributeMaxDynamicSharedMemorySize, smem1);
    cudaFuncSetAttribute(gemm2_kernel, cudaFuncAttributeMaxDynamicSharedMemorySize, smem2);

    int n4 = out_size / 4;
    zero_kernel<<<(n4 + 255) / 256, 256>>>((float4*)out, n4);
    routing_kernel<<<1, 1024>>>(sel, rw);
    gemm1_kernel<<<dim3(TK / BM, F_DIM / BN, N_EXP), 256, smem1>>>(X, Wgu);
    gemm2_kernel<<<dim3(TK / BM, D_DIM / BN, N_EXP), 256, smem2>>>(Wd, out);
}